// round 3
// baseline (speedup 1.0000x reference)
#include <cuda_runtime.h>
#include <cuda_bf16.h>
#include <math.h>

// ---------------------------------------------------------------------------
// PhysicsAwareMSELoss — single fused kernel, one occupancy wave.
//   grid = statsBlocks (B*nChunk) + pairStrips (ceil(B^2/256))
//   stats blocks : per (sample, chunk) partial sums, float4 loads.
//   strip blocks : screen 256 pairs from smem scalars, compact survivors,
//                  warps cooperatively reduce only the needed pairs.
//   epilogue     : threadfence + ticket; last block combines, writes out[0].
// ---------------------------------------------------------------------------

#define MAXB   256
#define MAXCH  16
#define ALPHA  0.7f
#define BETA   0.3f
#define STRIP  256      // pairs screened per strip block

__device__ float g_part[7][MAXB * MAXCH];   // 0:mse 1:cnt 2:Sx 3:Sy 4:Sxy 5:Sxx 6:mono
__device__ float g_pairD[MAXB * MAXB];      // only mask-needed entries written
__device__ unsigned int g_ticket;           // zero-init; reset by last block

__device__ __forceinline__ float reluf(float x) { return fmaxf(x, 0.f); }

__device__ __forceinline__ void pair_masks(int mi, int mj,
                                           float sri, float srj,
                                           float ti, float tj,
                                           bool& tmask_ij, bool& smask_ij)
{
    bool same   = (mi == mj);
    float hi    = fmaxf(sri, srj);
    float lo    = fminf(sri, srj);
    float ratio = hi / (lo + 1e-8f);
    float tdiff = ti - tj;
    tmask_ij = same && (ratio <= 1.2f) && (fabsf(tdiff) >= 10.f) && (tdiff > 0.f);
    smask_ij = same && (fabsf(tdiff) <= 10.f) && (ratio >= 1.2f) && (sri > srj);
}

__global__ void __launch_bounds__(256)
fused_kernel(const float* __restrict__ pred,
             const float* __restrict__ target,
             const int*   __restrict__ mat,
             const float* __restrict__ strain,
             const float* __restrict__ E,
             const float* __restrict__ temp,
             const float* __restrict__ sr,
             const float* __restrict__ w,
             float* __restrict__ out,
             int B, int S, int nChunk, int statsBlocks)
{
    const int tid  = threadIdx.x;
    const int lane = tid & 31;
    const int wid  = tid >> 5;

    __shared__ float sh[8][64];        // cross-warp reduce scratch (8 arrays x 8 warps)
    __shared__ bool  sh_last;
    __shared__ int   s_list[STRIP];
    __shared__ int   s_cnt;
    __shared__ int   s_mat[MAXB];
    __shared__ float s_sr[MAXB];
    __shared__ float s_temp[MAXB];

    // =================== role 1: per-sample stats (chunked) ===================
    if (blockIdx.x < statsBlocks) {
        const int b = blockIdx.x / nChunk;
        const int c = blockIdx.x % nChunk;
        const float* p = pred   + (size_t)b * S;
        const float* t = target + (size_t)b * S;
        const float* e = strain + (size_t)b * S;

        float v[7];                    // d2,cnt,sx,sy,sxy,sxx,mono
        #pragma unroll
        for (int k = 0; k < 7; k++) v[k] = 0.f;

        const int e0 = c * 1024 + tid * 4;   // chunk = 256 threads * 4 elems
        if (e0 + 3 < S) {
            float4 pv = *reinterpret_cast<const float4*>(p + e0);
            float4 tv = *reinterpret_cast<const float4*>(t + e0);
            float4 ev = *reinterpret_cast<const float4*>(e + e0);

            float dx = pv.x - tv.x, dy = pv.y - tv.y, dz = pv.z - tv.z, dw = pv.w - tv.w;
            v[0] = dx*dx + dy*dy + dz*dz + dw*dw;

            if (ev.x < 0.02f) { v[1] += 1.f; v[2] += ev.x; v[3] += pv.x; v[4] += ev.x*pv.x; v[5] += ev.x*ev.x; }
            if (ev.y < 0.02f) { v[1] += 1.f; v[2] += ev.y; v[3] += pv.y; v[4] += ev.y*pv.y; v[5] += ev.y*ev.y; }
            if (ev.z < 0.02f) { v[1] += 1.f; v[2] += ev.z; v[3] += pv.z; v[4] += ev.z*pv.z; v[5] += ev.z*ev.z; }
            if (ev.w < 0.02f) { v[1] += 1.f; v[2] += ev.w; v[3] += pv.w; v[4] += ev.w*pv.w; v[5] += ev.w*ev.w; }

            v[6] = reluf(pv.x - pv.y) + reluf(pv.y - pv.z) + reluf(pv.z - pv.w);
            float nxt = __shfl_down_sync(0xFFFFFFFFu, pv.x, 1);
            if (lane == 31) nxt = (e0 + 4 < S) ? p[e0 + 4] : pv.w;  // pv.w => relu 0
            v[6] += reluf(pv.w - nxt);
        } else if (e0 < S) {
            for (int i = e0; i < S && i < e0 + 4; i++) {
                float pv = p[i], tv = t[i], ev = e[i];
                float d = pv - tv; v[0] += d * d;
                if (ev < 0.02f) { v[1] += 1.f; v[2] += ev; v[3] += pv; v[4] += ev*pv; v[5] += ev*ev; }
                if (i < S - 1) v[6] += reluf(pv - p[i + 1]);
            }
        }

        // warp shuffle reduce, then 8-warp combine
        #pragma unroll
        for (int k = 0; k < 7; k++) {
            #pragma unroll
            for (int off = 16; off > 0; off >>= 1)
                v[k] += __shfl_xor_sync(0xFFFFFFFFu, v[k], off);
        }
        if (lane == 0) {
            #pragma unroll
            for (int k = 0; k < 7; k++) sh[k][wid] = v[k];
        }
        __syncthreads();
        if (wid == 0) {
            #pragma unroll
            for (int k = 0; k < 7; k++) {
                float x = (lane < 8) ? sh[k][lane] : 0.f;
                #pragma unroll
                for (int off = 4; off > 0; off >>= 1)
                    x += __shfl_xor_sync(0xFFFFFFFFu, x, off);
                if (lane == 0) g_part[k][b * nChunk + c] = x;
            }
        }
    }
    // =================== role 2: strip of pairs (screen + sparse reduce) ========
    else {
        const int strip = blockIdx.x - statsBlocks;
        const int totalPairs = B * B;
        const int base = strip * STRIP;
        const int end  = min(base + STRIP, totalPairs);

        if (tid == 0) s_cnt = 0;
        for (int b = tid; b < B; b += 256) {
            s_mat[b]  = mat[b];
            s_sr[b]   = sr[b];
            s_temp[b] = temp[b];
        }
        __syncthreads();

        for (int idx = base + tid; idx < end; idx += 256) {
            const int i = idx / B;
            const int j = idx - i * B;
            // need D[i,j] iff tmask(i,j) or smask(j,i)
            bool t_ij, sd, td, s_ji;
            pair_masks(s_mat[i], s_mat[j], s_sr[i], s_sr[j], s_temp[i], s_temp[j], t_ij, sd);
            pair_masks(s_mat[j], s_mat[i], s_sr[j], s_sr[i], s_temp[j], s_temp[i], td, s_ji);
            if (t_ij || s_ji) {
                int pos = atomicAdd(&s_cnt, 1);   // order irrelevant: unique output slots
                s_list[pos] = idx;
            }
        }
        __syncthreads();

        const int cnt = s_cnt;
        for (int li = wid; li < cnt; li += 8) {   // one warp per surviving pair
            const int idx = s_list[li];
            const int i = idx / B;
            const int j = idx - i * B;
            const float4* si = reinterpret_cast<const float4*>(pred + (size_t)i * S);
            const float4* sj = reinterpret_cast<const float4*>(pred + (size_t)j * S);
            const int S4 = S >> 2;
            float acc = 0.f;
            #pragma unroll 4
            for (int k = lane; k < S4; k += 32) {
                float4 a = si[k], bq = sj[k];
                acc += reluf(a.x - bq.x) + reluf(a.y - bq.y)
                     + reluf(a.z - bq.z) + reluf(a.w - bq.w);
            }
            #pragma unroll
            for (int off = 16; off > 0; off >>= 1)
                acc += __shfl_xor_sync(0xFFFFFFFFu, acc, off);
            if (lane == 0) g_pairD[idx] = acc / (float)S;
        }
        __syncthreads();
    }

    // =================== epilogue: last block finishes ===================
    __threadfence();
    if (tid == 0) {
        unsigned int v = atomicAdd(&g_ticket, 1u);
        sh_last = (v == gridDim.x - 1);
    }
    __syncthreads();
    if (!sh_last) return;
    __threadfence();

    // ---- final combine (last-arriving block, 256 threads) ----
    float acc8[8];
    #pragma unroll
    for (int k = 0; k < 8; k++) acc8[k] = 0.f;
    // acc8: 0:mse_p 1:el_sum 2:el_cnt 3:mono_p 4:tsum 5:tcnt 6:ssum 7:scnt

    for (int b = tid; b < B; b += 256) {
        float mse = 0.f, cnt = 0.f, Sx = 0.f, Sy = 0.f, Sxy = 0.f, Sxx = 0.f, mono = 0.f;
        for (int c = 0; c < nChunk; c++) {
            const int slot = b * nChunk + c;
            mse += g_part[0][slot]; cnt += g_part[1][slot];
            Sx  += g_part[2][slot]; Sy  += g_part[3][slot];
            Sxy += g_part[4][slot]; Sxx += g_part[5][slot];
            mono+= g_part[6][slot];
        }
        acc8[0] += (mse / (float)S) * w[mat[b]];
        acc8[3] += mono;
        if (cnt >= 2.f) {
            float safe  = fmaxf(cnt, 1.f);
            float eps_m = Sx / safe;
            float sig_m = Sy / safe;
            float cov = Sxy - sig_m * Sx - eps_m * Sy + cnt * eps_m * sig_m;
            float var = Sxx - 2.f * eps_m * Sx + cnt * eps_m * eps_m;
            float et  = E[b] * 1000.f;
            acc8[1] += fabsf(cov / (var + 1e-8f) - et) / (et + 1e-8f);
            acc8[2] += 1.f;
        }
    }

    // reload scalars into smem for the re-screen
    for (int b = tid; b < B; b += 256) {
        s_mat[b]  = mat[b];
        s_sr[b]   = sr[b];
        s_temp[b] = temp[b];
    }
    __syncthreads();

    for (int idx = tid; idx < B * B; idx += 256) {
        const int i = idx / B;
        const int j = idx - i * B;
        bool t_ij, s_ij;
        pair_masks(s_mat[i], s_mat[j], s_sr[i], s_sr[j], s_temp[i], s_temp[j], t_ij, s_ij);
        if (t_ij) { acc8[4] += g_pairD[i * B + j]; acc8[5] += 1.f; }
        if (s_ij) { acc8[6] += g_pairD[j * B + i]; acc8[7] += 1.f; }
    }

    #pragma unroll
    for (int k = 0; k < 8; k++) {
        #pragma unroll
        for (int off = 16; off > 0; off >>= 1)
            acc8[k] += __shfl_xor_sync(0xFFFFFFFFu, acc8[k], off);
    }
    if (lane == 0) {
        #pragma unroll
        for (int k = 0; k < 8; k++) sh[k][wid] = acc8[k];
    }
    __syncthreads();
    if (tid == 0) {
        float r[8];
        #pragma unroll
        for (int k = 0; k < 8; k++) {
            r[k] = 0.f;
            for (int q = 0; q < 8; q++) r[k] += sh[k][q];
        }
        float mse_loss  = r[0] / (float)B;
        float elastic   = (r[2] > 0.f) ? r[1] / fmaxf(r[2], 1.f) : 0.f;
        float mono      = r[3] / (float)(B * (S - 1));
        float temp_loss = (r[5] > 0.f) ? r[4] / fmaxf(r[5], 1.f) : 0.f;
        float sr_loss   = (r[7] > 0.f) ? r[6] / fmaxf(r[7], 1.f) : 0.f;
        out[0] = ALPHA * mse_loss + BETA * (elastic + mono + temp_loss + sr_loss);
        g_ticket = 0;   // reset for next graph replay
    }
}

// --------------------------------------------------------------------------
extern "C" void kernel_launch(void* const* d_in, const int* in_sizes, int n_in,
                              void* d_out, int out_size)
{
    const float* pred   = (const float*)d_in[0];
    const float* target = (const float*)d_in[1];
    const int*   matid  = (const int*)  d_in[2];
    const float* strain = (const float*)d_in[3];
    const float* E_GPa  = (const float*)d_in[4];
    const float* temp   = (const float*)d_in[5];
    const float* sr     = (const float*)d_in[6];
    const float* mw     = (const float*)d_in[7];
    float* out = (float*)d_out;

    const int B = in_sizes[2];          // material_ids count
    const int S = in_sizes[0] / B;      // pred = B*S

    const int nChunk      = (S + 1023) / 1024;            // 1024 elems / chunk
    const int statsBlocks = B * nChunk;                    // 256 for B=128,S=2048
    const int pairStrips  = (B * B + STRIP - 1) / STRIP;   // 64 for B=128
    const int grid        = statsBlocks + pairStrips;      // 320 blocks: 1 wave

    fused_kernel<<<grid, 256>>>(pred, target, matid, strain, E_GPa, temp, sr, mw,
                                out, B, S, nChunk, statsBlocks);
}

// round 4
// speedup vs baseline: 1.5444x; 1.5444x over previous
#include <cuda_runtime.h>
#include <cuda_bf16.h>
#include <math.h>

// ---------------------------------------------------------------------------
// PhysicsAwareMSELoss — two graph-serialized kernels, no device-wide fences.
//   kernel 1 (work): stats blocks (per sample-chunk partial sums, float4) +
//                    strip blocks (screen 256 pairs from smem scalars,
//                    compact survivors, warp-reduce only needed pairs).
//   kernel 2 (final): one block combines partials -> out[0].
// Synchronization = the kernel boundary (graph edge). No tickets, no membars.
// ---------------------------------------------------------------------------

#define MAXB   256
#define MAXCH  16
#define ALPHA  0.7f
#define BETA   0.3f
#define STRIP  256      // pairs screened per strip block

__device__ float g_part[7][MAXB * MAXCH];   // 0:mse 1:cnt 2:Sx 3:Sy 4:Sxy 5:Sxx 6:mono
__device__ float g_pairD[MAXB * MAXB];      // only mask-needed entries written

__device__ __forceinline__ float reluf(float x) { return fmaxf(x, 0.f); }

__device__ __forceinline__ void pair_masks(int mi, int mj,
                                           float sri, float srj,
                                           float ti, float tj,
                                           bool& tmask_ij, bool& smask_ij)
{
    bool same   = (mi == mj);
    float hi    = fmaxf(sri, srj);
    float lo    = fminf(sri, srj);
    float ratio = hi / (lo + 1e-8f);
    float tdiff = ti - tj;
    tmask_ij = same && (ratio <= 1.2f) && (fabsf(tdiff) >= 10.f) && (tdiff > 0.f);
    smask_ij = same && (fabsf(tdiff) <= 10.f) && (ratio >= 1.2f) && (sri > srj);
}

// ============================ kernel 1: work ================================
__global__ void __launch_bounds__(256)
work_kernel(const float* __restrict__ pred,
            const float* __restrict__ target,
            const int*   __restrict__ mat,
            const float* __restrict__ strain,
            const float* __restrict__ temp,
            const float* __restrict__ sr,
            int B, int S, int nChunk, int statsBlocks)
{
    const int tid  = threadIdx.x;
    const int lane = tid & 31;
    const int wid  = tid >> 5;

    if (blockIdx.x < statsBlocks) {
        // ---------------- per-sample stats (chunked) ----------------
        __shared__ float sh[7][8];
        const int b = blockIdx.x / nChunk;
        const int c = blockIdx.x % nChunk;
        const float* p = pred   + (size_t)b * S;
        const float* t = target + (size_t)b * S;
        const float* e = strain + (size_t)b * S;

        float v[7];
        #pragma unroll
        for (int k = 0; k < 7; k++) v[k] = 0.f;

        const int e0 = c * 1024 + tid * 4;
        if (e0 + 3 < S) {
            float4 pv = *reinterpret_cast<const float4*>(p + e0);
            float4 tv = *reinterpret_cast<const float4*>(t + e0);
            float4 ev = *reinterpret_cast<const float4*>(e + e0);

            float dx = pv.x - tv.x, dy = pv.y - tv.y, dz = pv.z - tv.z, dw = pv.w - tv.w;
            v[0] = dx*dx + dy*dy + dz*dz + dw*dw;

            if (ev.x < 0.02f) { v[1] += 1.f; v[2] += ev.x; v[3] += pv.x; v[4] += ev.x*pv.x; v[5] += ev.x*ev.x; }
            if (ev.y < 0.02f) { v[1] += 1.f; v[2] += ev.y; v[3] += pv.y; v[4] += ev.y*pv.y; v[5] += ev.y*ev.y; }
            if (ev.z < 0.02f) { v[1] += 1.f; v[2] += ev.z; v[3] += pv.z; v[4] += ev.z*pv.z; v[5] += ev.z*ev.z; }
            if (ev.w < 0.02f) { v[1] += 1.f; v[2] += ev.w; v[3] += pv.w; v[4] += ev.w*pv.w; v[5] += ev.w*ev.w; }

            v[6] = reluf(pv.x - pv.y) + reluf(pv.y - pv.z) + reluf(pv.z - pv.w);
            float nxt = __shfl_down_sync(0xFFFFFFFFu, pv.x, 1);
            if (lane == 31) nxt = (e0 + 4 < S) ? p[e0 + 4] : pv.w;  // pv.w => relu 0
            v[6] += reluf(pv.w - nxt);
        } else if (e0 < S) {
            for (int i = e0; i < S && i < e0 + 4; i++) {
                float pv = p[i], tv = t[i], ev = e[i];
                float d = pv - tv; v[0] += d * d;
                if (ev < 0.02f) { v[1] += 1.f; v[2] += ev; v[3] += pv; v[4] += ev*pv; v[5] += ev*ev; }
                if (i < S - 1) v[6] += reluf(pv - p[i + 1]);
            }
        }

        #pragma unroll
        for (int k = 0; k < 7; k++) {
            #pragma unroll
            for (int off = 16; off > 0; off >>= 1)
                v[k] += __shfl_xor_sync(0xFFFFFFFFu, v[k], off);
        }
        if (lane == 0) {
            #pragma unroll
            for (int k = 0; k < 7; k++) sh[k][wid] = v[k];
        }
        __syncthreads();
        if (wid == 0 && lane < 8) {
            #pragma unroll
            for (int k = 0; k < 7; k++) {
                float x = sh[k][lane];
                #pragma unroll
                for (int off = 4; off > 0; off >>= 1)
                    x += __shfl_xor_sync(0x000000FFu, x, off);
                if (lane == 0) g_part[k][b * nChunk + c] = x;
            }
        }
    } else {
        // ---------------- strip of pairs: screen + sparse reduce ----------------
        __shared__ int   s_list[STRIP];
        __shared__ int   s_cnt;
        __shared__ int   s_mat[MAXB];
        __shared__ float s_sr[MAXB];
        __shared__ float s_temp[MAXB];

        const int strip = blockIdx.x - statsBlocks;
        const int totalPairs = B * B;
        const int base = strip * STRIP;
        const int end  = min(base + STRIP, totalPairs);

        if (tid == 0) s_cnt = 0;
        for (int b = tid; b < B; b += 256) {
            s_mat[b]  = mat[b];
            s_sr[b]   = sr[b];
            s_temp[b] = temp[b];
        }
        __syncthreads();

        for (int idx = base + tid; idx < end; idx += 256) {
            const int i = idx / B;
            const int j = idx - i * B;
            // need D[i,j] iff tmask(i,j) or smask(j,i)
            bool t_ij, sd, td, s_ji;
            pair_masks(s_mat[i], s_mat[j], s_sr[i], s_sr[j], s_temp[i], s_temp[j], t_ij, sd);
            pair_masks(s_mat[j], s_mat[i], s_sr[j], s_sr[i], s_temp[j], s_temp[i], td, s_ji);
            if (t_ij || s_ji) {
                int pos = atomicAdd(&s_cnt, 1);   // unique slots; order irrelevant
                s_list[pos] = idx;
            }
        }
        __syncthreads();

        const int cnt = s_cnt;
        for (int li = wid; li < cnt; li += 8) {
            const int idx = s_list[li];
            const int i = idx / B;
            const int j = idx - i * B;
            const float4* si = reinterpret_cast<const float4*>(pred + (size_t)i * S);
            const float4* sj = reinterpret_cast<const float4*>(pred + (size_t)j * S);
            const int S4 = S >> 2;
            float acc = 0.f;
            #pragma unroll 4
            for (int k = lane; k < S4; k += 32) {
                float4 a = si[k], bq = sj[k];
                acc += reluf(a.x - bq.x) + reluf(a.y - bq.y)
                     + reluf(a.z - bq.z) + reluf(a.w - bq.w);
            }
            #pragma unroll
            for (int off = 16; off > 0; off >>= 1)
                acc += __shfl_xor_sync(0xFFFFFFFFu, acc, off);
            if (lane == 0) g_pairD[idx] = acc / (float)S;
        }
    }
}

// ============================ kernel 2: final ================================
__global__ void __launch_bounds__(256)
final_kernel(const int*   __restrict__ mat,
             const float* __restrict__ w,
             const float* __restrict__ E,
             const float* __restrict__ temp,
             const float* __restrict__ sr,
             float* __restrict__ out,
             int B, int S, int nChunk)
{
    const int tid  = threadIdx.x;
    const int lane = tid & 31;
    const int wid  = tid >> 5;

    __shared__ float sh[8][8];
    __shared__ int   s_mat[MAXB];
    __shared__ float s_sr[MAXB];
    __shared__ float s_temp[MAXB];

    for (int b = tid; b < B; b += 256) {
        s_mat[b]  = mat[b];
        s_sr[b]   = sr[b];
        s_temp[b] = temp[b];
    }
    __syncthreads();

    float acc8[8];   // 0:mse_p 1:el_sum 2:el_cnt 3:mono_p 4:tsum 5:tcnt 6:ssum 7:scnt
    #pragma unroll
    for (int k = 0; k < 8; k++) acc8[k] = 0.f;

    for (int b = tid; b < B; b += 256) {
        float mse = 0.f, cnt = 0.f, Sx = 0.f, Sy = 0.f, Sxy = 0.f, Sxx = 0.f, mono = 0.f;
        for (int c = 0; c < nChunk; c++) {
            const int slot = b * nChunk + c;
            mse += g_part[0][slot]; cnt += g_part[1][slot];
            Sx  += g_part[2][slot]; Sy  += g_part[3][slot];
            Sxy += g_part[4][slot]; Sxx += g_part[5][slot];
            mono+= g_part[6][slot];
        }
        acc8[0] += (mse / (float)S) * w[s_mat[b]];
        acc8[3] += mono;
        if (cnt >= 2.f) {
            float safe  = fmaxf(cnt, 1.f);
            float eps_m = Sx / safe;
            float sig_m = Sy / safe;
            float cov = Sxy - sig_m * Sx - eps_m * Sy + cnt * eps_m * sig_m;
            float var = Sxx - 2.f * eps_m * Sx + cnt * eps_m * eps_m;
            float et  = E[b] * 1000.f;
            acc8[1] += fabsf(cov / (var + 1e-8f) - et) / (et + 1e-8f);
            acc8[2] += 1.f;
        }
    }

    for (int idx = tid; idx < B * B; idx += 256) {
        const int i = idx / B;
        const int j = idx - i * B;
        bool t_ij, s_ij;
        pair_masks(s_mat[i], s_mat[j], s_sr[i], s_sr[j], s_temp[i], s_temp[j], t_ij, s_ij);
        if (t_ij) { acc8[4] += g_pairD[i * B + j]; acc8[5] += 1.f; }
        if (s_ij) { acc8[6] += g_pairD[j * B + i]; acc8[7] += 1.f; }
    }

    #pragma unroll
    for (int k = 0; k < 8; k++) {
        #pragma unroll
        for (int off = 16; off > 0; off >>= 1)
            acc8[k] += __shfl_xor_sync(0xFFFFFFFFu, acc8[k], off);
    }
    if (lane == 0) {
        #pragma unroll
        for (int k = 0; k < 8; k++) sh[k][wid] = acc8[k];
    }
    __syncthreads();
    if (tid == 0) {
        float r[8];
        #pragma unroll
        for (int k = 0; k < 8; k++) {
            r[k] = 0.f;
            #pragma unroll
            for (int q = 0; q < 8; q++) r[k] += sh[k][q];
        }
        float mse_loss  = r[0] / (float)B;
        float elastic   = (r[2] > 0.f) ? r[1] / fmaxf(r[2], 1.f) : 0.f;
        float mono      = r[3] / (float)(B * (S - 1));
        float temp_loss = (r[5] > 0.f) ? r[4] / fmaxf(r[5], 1.f) : 0.f;
        float sr_loss   = (r[7] > 0.f) ? r[6] / fmaxf(r[7], 1.f) : 0.f;
        out[0] = ALPHA * mse_loss + BETA * (elastic + mono + temp_loss + sr_loss);
    }
}

// --------------------------------------------------------------------------
extern "C" void kernel_launch(void* const* d_in, const int* in_sizes, int n_in,
                              void* d_out, int out_size)
{
    const float* pred   = (const float*)d_in[0];
    const float* target = (const float*)d_in[1];
    const int*   matid  = (const int*)  d_in[2];
    const float* strain = (const float*)d_in[3];
    const float* E_GPa  = (const float*)d_in[4];
    const float* temp   = (const float*)d_in[5];
    const float* sr     = (const float*)d_in[6];
    const float* mw     = (const float*)d_in[7];
    float* out = (float*)d_out;

    const int B = in_sizes[2];          // material_ids count
    const int S = in_sizes[0] / B;      // pred = B*S

    const int nChunk      = (S + 1023) / 1024;            // 1024 elems / chunk
    const int statsBlocks = B * nChunk;                    // 256 for B=128,S=2048
    const int pairStrips  = (B * B + STRIP - 1) / STRIP;   // 64 for B=128
    const int grid        = statsBlocks + pairStrips;      // 320 blocks

    work_kernel<<<grid, 256>>>(pred, target, matid, strain, temp, sr,
                               B, S, nChunk, statsBlocks);
    final_kernel<<<1, 256>>>(matid, mw, E_GPa, temp, sr, out, B, S, nChunk);
}

// round 5
// speedup vs baseline: 2.7255x; 1.7647x over previous
#include <cuda_runtime.h>
#include <cuda_bf16.h>
#include <math.h>

// ---------------------------------------------------------------------------
// PhysicsAwareMSELoss — two graph-serialized kernels.
//   kernel 1 (work):
//     stats blocks : per (sample, chunk) partial sums, float4 loads.
//     strip blocks : each warp screens 32 fixed pairs (smem scalars),
//                    ballot-walks survivors in lane order, warp-reduces
//                    D only for needed pairs, accumulates (tsum,tcnt,
//                    ssum,scnt) per strip -> g_pairAcc.  Deterministic:
//                    fixed pair->lane map, fixed walk order, no atomics.
//   kernel 2 (final): one block combines g_part + g_pairAcc -> out[0].
// ---------------------------------------------------------------------------

#define MAXB    256
#define MAXCH   16
#define MAXSTRP 256
#define ALPHA   0.7f
#define BETA    0.3f
#define STRIP   256     // pairs per strip block (8 warps x 32)

__device__ float g_part[7][MAXB * MAXCH];   // 0:mse 1:cnt 2:Sx 3:Sy 4:Sxy 5:Sxx 6:mono
__device__ float g_pairAcc[4][MAXSTRP];     // 0:tsum 1:tcnt 2:ssum 3:scnt per strip

__device__ __forceinline__ float reluf(float x) { return fmaxf(x, 0.f); }

__device__ __forceinline__ void pair_masks(int mi, int mj,
                                           float sri, float srj,
                                           float ti, float tj,
                                           bool& tmask_ij, bool& smask_ij)
{
    bool same   = (mi == mj);
    float hi    = fmaxf(sri, srj);
    float lo    = fminf(sri, srj);
    float ratio = hi / (lo + 1e-8f);
    float tdiff = ti - tj;
    tmask_ij = same && (ratio <= 1.2f) && (fabsf(tdiff) >= 10.f) && (tdiff > 0.f);
    smask_ij = same && (fabsf(tdiff) <= 10.f) && (ratio >= 1.2f) && (sri > srj);
}

// ============================ kernel 1: work ================================
__global__ void __launch_bounds__(256)
work_kernel(const float* __restrict__ pred,
            const float* __restrict__ target,
            const int*   __restrict__ mat,
            const float* __restrict__ strain,
            const float* __restrict__ temp,
            const float* __restrict__ sr,
            int B, int S, int nChunk, int statsBlocks)
{
    const int tid  = threadIdx.x;
    const int lane = tid & 31;
    const int wid  = tid >> 5;

    if (blockIdx.x < statsBlocks) {
        // ---------------- per-sample stats (chunked) ----------------
        __shared__ float sh[7][8];
        const int b = blockIdx.x / nChunk;
        const int c = blockIdx.x % nChunk;
        const float* p = pred   + (size_t)b * S;
        const float* t = target + (size_t)b * S;
        const float* e = strain + (size_t)b * S;

        float v[7];
        #pragma unroll
        for (int k = 0; k < 7; k++) v[k] = 0.f;

        const int e0 = c * 1024 + tid * 4;
        if (e0 + 3 < S) {
            float4 pv = *reinterpret_cast<const float4*>(p + e0);
            float4 tv = *reinterpret_cast<const float4*>(t + e0);
            float4 ev = *reinterpret_cast<const float4*>(e + e0);

            float dx = pv.x - tv.x, dy = pv.y - tv.y, dz = pv.z - tv.z, dw = pv.w - tv.w;
            v[0] = dx*dx + dy*dy + dz*dz + dw*dw;

            if (ev.x < 0.02f) { v[1] += 1.f; v[2] += ev.x; v[3] += pv.x; v[4] += ev.x*pv.x; v[5] += ev.x*ev.x; }
            if (ev.y < 0.02f) { v[1] += 1.f; v[2] += ev.y; v[3] += pv.y; v[4] += ev.y*pv.y; v[5] += ev.y*ev.y; }
            if (ev.z < 0.02f) { v[1] += 1.f; v[2] += ev.z; v[3] += pv.z; v[4] += ev.z*pv.z; v[5] += ev.z*ev.z; }
            if (ev.w < 0.02f) { v[1] += 1.f; v[2] += ev.w; v[3] += pv.w; v[4] += ev.w*pv.w; v[5] += ev.w*ev.w; }

            v[6] = reluf(pv.x - pv.y) + reluf(pv.y - pv.z) + reluf(pv.z - pv.w);
            float nxt = __shfl_down_sync(0xFFFFFFFFu, pv.x, 1);
            if (lane == 31) nxt = (e0 + 4 < S) ? p[e0 + 4] : pv.w;  // pv.w => relu 0
            v[6] += reluf(pv.w - nxt);
        } else if (e0 < S) {
            for (int i = e0; i < S && i < e0 + 4; i++) {
                float pv = p[i], tv = t[i], ev = e[i];
                float d = pv - tv; v[0] += d * d;
                if (ev < 0.02f) { v[1] += 1.f; v[2] += ev; v[3] += pv; v[4] += ev*pv; v[5] += ev*ev; }
                if (i < S - 1) v[6] += reluf(pv - p[i + 1]);
            }
        }

        #pragma unroll
        for (int k = 0; k < 7; k++) {
            #pragma unroll
            for (int off = 16; off > 0; off >>= 1)
                v[k] += __shfl_xor_sync(0xFFFFFFFFu, v[k], off);
        }
        if (lane == 0) {
            #pragma unroll
            for (int k = 0; k < 7; k++) sh[k][wid] = v[k];
        }
        __syncthreads();
        if (wid == 0 && lane < 8) {
            #pragma unroll
            for (int k = 0; k < 7; k++) {
                float x = sh[k][lane];
                #pragma unroll
                for (int off = 4; off > 0; off >>= 1)
                    x += __shfl_xor_sync(0x000000FFu, x, off);
                if (lane == 0) g_part[k][b * nChunk + c] = x;
            }
        }
    } else {
        // ------------- strip of pairs: screen + sparse reduce + accumulate -------------
        __shared__ float shp[4][8];
        __shared__ int   s_mat[MAXB];
        __shared__ float s_sr[MAXB];
        __shared__ float s_temp[MAXB];

        const int strip = blockIdx.x - statsBlocks;
        const int totalPairs = B * B;

        for (int b = tid; b < B; b += 256) {
            s_mat[b]  = mat[b];
            s_sr[b]   = sr[b];
            s_temp[b] = temp[b];
        }
        __syncthreads();

        // each thread screens exactly one pair (fixed map: idx = strip*STRIP + tid)
        const int idx = strip * STRIP + tid;
        bool t_ij = false, s_ji = false;
        int  myi = 0, myj = 0;
        if (idx < totalPairs) {
            myi = idx / B;
            myj = idx - myi * B;
            bool sd, td;
            pair_masks(s_mat[myi], s_mat[myj], s_sr[myi], s_sr[myj],
                       s_temp[myi], s_temp[myj], t_ij, sd);
            pair_masks(s_mat[myj], s_mat[myi], s_sr[myj], s_sr[myi],
                       s_temp[myj], s_temp[myi], td, s_ji);
        }
        const bool need = t_ij || s_ji;

        // ballot-walk survivors in lane order (deterministic)
        unsigned bal = __ballot_sync(0xFFFFFFFFu, need);
        float tsum = 0.f, tcnt = 0.f, ssum = 0.f, scnt = 0.f;
        const int S4 = S >> 2;
        while (bal) {
            const int src = __ffs(bal) - 1;
            bal &= bal - 1;
            const int i  = __shfl_sync(0xFFFFFFFFu, myi, src);
            const int j  = __shfl_sync(0xFFFFFFFFu, myj, src);
            const int tt = __shfl_sync(0xFFFFFFFFu, (int)t_ij, src);
            const int ss = __shfl_sync(0xFFFFFFFFu, (int)s_ji, src);

            const float4* si = reinterpret_cast<const float4*>(pred + (size_t)i * S);
            const float4* sj = reinterpret_cast<const float4*>(pred + (size_t)j * S);
            float acc = 0.f;
            #pragma unroll 4
            for (int k = lane; k < S4; k += 32) {
                float4 a = si[k], bq = sj[k];
                acc += reluf(a.x - bq.x) + reluf(a.y - bq.y)
                     + reluf(a.z - bq.z) + reluf(a.w - bq.w);
            }
            #pragma unroll
            for (int off = 16; off > 0; off >>= 1)
                acc += __shfl_xor_sync(0xFFFFFFFFu, acc, off);
            const float D = acc / (float)S;          // same on all lanes
            if (tt) { tsum += D; tcnt += 1.f; }
            if (ss) { ssum += D; scnt += 1.f; }
        }

        // combine the 8 warps in fixed order; every strip writes its slot
        if (lane == 0) {
            shp[0][wid] = tsum; shp[1][wid] = tcnt;
            shp[2][wid] = ssum; shp[3][wid] = scnt;
        }
        __syncthreads();
        if (tid == 0) {
            float r0 = 0.f, r1 = 0.f, r2 = 0.f, r3 = 0.f;
            #pragma unroll
            for (int q = 0; q < 8; q++) {
                r0 += shp[0][q]; r1 += shp[1][q];
                r2 += shp[2][q]; r3 += shp[3][q];
            }
            g_pairAcc[0][strip] = r0;
            g_pairAcc[1][strip] = r1;
            g_pairAcc[2][strip] = r2;
            g_pairAcc[3][strip] = r3;
        }
    }
}

// ============================ kernel 2: final ================================
__global__ void __launch_bounds__(256)
final_kernel(const int*   __restrict__ mat,
             const float* __restrict__ w,
             const float* __restrict__ E,
             float* __restrict__ out,
             int B, int S, int nChunk, int nStrips)
{
    const int tid  = threadIdx.x;
    const int lane = tid & 31;
    const int wid  = tid >> 5;

    __shared__ float sh[8][8];

    float acc8[8];   // 0:mse_p 1:el_sum 2:el_cnt 3:mono_p 4:tsum 5:tcnt 6:ssum 7:scnt
    #pragma unroll
    for (int k = 0; k < 8; k++) acc8[k] = 0.f;

    for (int b = tid; b < B; b += 256) {
        float mse = 0.f, cnt = 0.f, Sx = 0.f, Sy = 0.f, Sxy = 0.f, Sxx = 0.f, mono = 0.f;
        for (int c = 0; c < nChunk; c++) {
            const int slot = b * nChunk + c;
            mse += g_part[0][slot]; cnt += g_part[1][slot];
            Sx  += g_part[2][slot]; Sy  += g_part[3][slot];
            Sxy += g_part[4][slot]; Sxx += g_part[5][slot];
            mono+= g_part[6][slot];
        }
        acc8[0] += (mse / (float)S) * w[mat[b]];
        acc8[3] += mono;
        if (cnt >= 2.f) {
            float safe  = fmaxf(cnt, 1.f);
            float eps_m = Sx / safe;
            float sig_m = Sy / safe;
            float cov = Sxy - sig_m * Sx - eps_m * Sy + cnt * eps_m * sig_m;
            float var = Sxx - 2.f * eps_m * Sx + cnt * eps_m * eps_m;
            float et  = E[b] * 1000.f;
            acc8[1] += fabsf(cov / (var + 1e-8f) - et) / (et + 1e-8f);
            acc8[2] += 1.f;
        }
    }

    for (int sidx = tid; sidx < nStrips; sidx += 256) {
        acc8[4] += g_pairAcc[0][sidx];
        acc8[5] += g_pairAcc[1][sidx];
        acc8[6] += g_pairAcc[2][sidx];
        acc8[7] += g_pairAcc[3][sidx];
    }

    #pragma unroll
    for (int k = 0; k < 8; k++) {
        #pragma unroll
        for (int off = 16; off > 0; off >>= 1)
            acc8[k] += __shfl_xor_sync(0xFFFFFFFFu, acc8[k], off);
    }
    if (lane == 0) {
        #pragma unroll
        for (int k = 0; k < 8; k++) sh[k][wid] = acc8[k];
    }
    __syncthreads();
    if (tid == 0) {
        float r[8];
        #pragma unroll
        for (int k = 0; k < 8; k++) {
            r[k] = 0.f;
            #pragma unroll
            for (int q = 0; q < 8; q++) r[k] += sh[k][q];
        }
        float mse_loss  = r[0] / (float)B;
        float elastic   = (r[2] > 0.f) ? r[1] / fmaxf(r[2], 1.f) : 0.f;
        float mono      = r[3] / (float)(B * (S - 1));
        float temp_loss = (r[5] > 0.f) ? r[4] / fmaxf(r[5], 1.f) : 0.f;
        float sr_loss   = (r[7] > 0.f) ? r[6] / fmaxf(r[7], 1.f) : 0.f;
        out[0] = ALPHA * mse_loss + BETA * (elastic + mono + temp_loss + sr_loss);
    }
}

// --------------------------------------------------------------------------
extern "C" void kernel_launch(void* const* d_in, const int* in_sizes, int n_in,
                              void* d_out, int out_size)
{
    const float* pred   = (const float*)d_in[0];
    const float* target = (const float*)d_in[1];
    const int*   matid  = (const int*)  d_in[2];
    const float* strain = (const float*)d_in[3];
    const float* E_GPa  = (const float*)d_in[4];
    const float* temp   = (const float*)d_in[5];
    const float* sr     = (const float*)d_in[6];
    const float* mw     = (const float*)d_in[7];
    float* out = (float*)d_out;

    const int B = in_sizes[2];          // material_ids count
    const int S = in_sizes[0] / B;      // pred = B*S

    const int nChunk      = (S + 1023) / 1024;            // 1024 elems / chunk
    const int statsBlocks = B * nChunk;                    // 256 for B=128,S=2048
    const int pairStrips  = (B * B + STRIP - 1) / STRIP;   // 64 for B=128
    const int grid        = statsBlocks + pairStrips;      // 320 blocks

    work_kernel<<<grid, 256>>>(pred, target, matid, strain, temp, sr,
                               B, S, nChunk, statsBlocks);
    final_kernel<<<1, 256>>>(matid, mw, E_GPa, out, B, S, nChunk, pairStrips);
}

// round 6
// speedup vs baseline: 3.0217x; 1.1087x over previous
#include <cuda_runtime.h>
#include <cuda_bf16.h>
#include <math.h>

// ---------------------------------------------------------------------------
// PhysicsAwareMSELoss — two graph-serialized kernels.
//   kernel 1 (work):
//     sample blocks: one block per sample; 256 threads x 8 elems (2xfloat4).
//                    Block reduces 7 sums, thread 0 finishes ALL per-sample
//                    math (weighted mse, elastic slope err, mono) -> g_samp.
//     strip blocks : each warp screens 32 fixed pairs (smem scalars),
//                    ballot-walks survivors in lane order, warp-reduces D
//                    for needed pairs only -> g_pairAcc[strip]. Deterministic.
//   kernel 2 (final): one block sums 4*B + 4*strips floats -> out[0].
// ---------------------------------------------------------------------------

#define MAXB    256
#define MAXSTRP 256
#define ALPHA   0.7f
#define BETA    0.3f
#define STRIP   256     // pairs per strip block (8 warps x 32)

__device__ float g_samp[4][MAXB];       // 0:wmse 1:el_err 2:el_valid 3:mono
__device__ float g_pairAcc[4][MAXSTRP]; // 0:tsum 1:tcnt 2:ssum 3:scnt per strip

__device__ __forceinline__ float reluf(float x) { return fmaxf(x, 0.f); }

__device__ __forceinline__ void pair_masks(int mi, int mj,
                                           float sri, float srj,
                                           float ti, float tj,
                                           bool& tmask_ij, bool& smask_ij)
{
    bool same   = (mi == mj);
    float hi    = fmaxf(sri, srj);
    float lo    = fminf(sri, srj);
    float ratio = hi / (lo + 1e-8f);
    float tdiff = ti - tj;
    tmask_ij = same && (ratio <= 1.2f) && (fabsf(tdiff) >= 10.f) && (tdiff > 0.f);
    smask_ij = same && (fabsf(tdiff) <= 10.f) && (ratio >= 1.2f) && (sri > srj);
}

// ============================ kernel 1: work ================================
__global__ void __launch_bounds__(256)
work_kernel(const float* __restrict__ pred,
            const float* __restrict__ target,
            const int*   __restrict__ mat,
            const float* __restrict__ strain,
            const float* __restrict__ E,
            const float* __restrict__ temp,
            const float* __restrict__ sr,
            const float* __restrict__ w,
            int B, int S)
{
    const int tid  = threadIdx.x;
    const int lane = tid & 31;
    const int wid  = tid >> 5;

    if (blockIdx.x < B) {
        // ---------------- one block per sample: full stats + per-sample math ----
        __shared__ float sh[7][8];
        const int b = blockIdx.x;
        const float* p = pred   + (size_t)b * S;
        const float* t = target + (size_t)b * S;
        const float* e = strain + (size_t)b * S;

        float v[7];   // d2, cnt, sx, sy, sxy, sxx, mono
        #pragma unroll
        for (int k = 0; k < 7; k++) v[k] = 0.f;

        for (int base = 0; base < S; base += 2048) {
            const int e0 = base + tid * 8;
            if (e0 + 7 < S) {
                float4 p0 = *reinterpret_cast<const float4*>(p + e0);
                float4 p1 = *reinterpret_cast<const float4*>(p + e0 + 4);
                float4 t0 = *reinterpret_cast<const float4*>(t + e0);
                float4 t1 = *reinterpret_cast<const float4*>(t + e0 + 4);
                float4 e0v = *reinterpret_cast<const float4*>(e + e0);
                float4 e1v = *reinterpret_cast<const float4*>(e + e0 + 4);

                float pv[8] = {p0.x,p0.y,p0.z,p0.w,p1.x,p1.y,p1.z,p1.w};
                float tv[8] = {t0.x,t0.y,t0.z,t0.w,t1.x,t1.y,t1.z,t1.w};
                float ev[8] = {e0v.x,e0v.y,e0v.z,e0v.w,e1v.x,e1v.y,e1v.z,e1v.w};

                #pragma unroll
                for (int q = 0; q < 8; q++) {
                    float d = pv[q] - tv[q];
                    v[0] += d * d;
                    if (ev[q] < 0.02f) {
                        v[1] += 1.f; v[2] += ev[q]; v[3] += pv[q];
                        v[4] += ev[q] * pv[q]; v[5] += ev[q] * ev[q];
                    }
                }
                #pragma unroll
                for (int q = 0; q < 7; q++)
                    v[6] += reluf(pv[q] - pv[q + 1]);
                // boundary: element e0+7 -> e0+8
                float nxt = __shfl_down_sync(0xFFFFFFFFu, pv[0], 1);
                if (lane == 31) nxt = (e0 + 8 < S) ? p[e0 + 8] : pv[7]; // => relu 0
                v[6] += reluf(pv[7] - nxt);
            } else if (e0 < S) {
                for (int i = e0; i < S && i < e0 + 8; i++) {
                    float pvv = p[i], tvv = t[i], evv = e[i];
                    float d = pvv - tvv; v[0] += d * d;
                    if (evv < 0.02f) { v[1] += 1.f; v[2] += evv; v[3] += pvv;
                                       v[4] += evv*pvv; v[5] += evv*evv; }
                    if (i < S - 1) v[6] += reluf(pvv - p[i + 1]);
                }
            }
        }

        #pragma unroll
        for (int k = 0; k < 7; k++) {
            #pragma unroll
            for (int off = 16; off > 0; off >>= 1)
                v[k] += __shfl_xor_sync(0xFFFFFFFFu, v[k], off);
        }
        if (lane == 0) {
            #pragma unroll
            for (int k = 0; k < 7; k++) sh[k][wid] = v[k];
        }
        __syncthreads();
        if (tid == 0) {
            float r[7];
            #pragma unroll
            for (int k = 0; k < 7; k++) {
                r[k] = 0.f;
                #pragma unroll
                for (int q = 0; q < 8; q++) r[k] += sh[k][q];
            }
            // per-sample math, all here:
            float wmse = (r[0] / (float)S) * w[mat[b]];
            float cnt = r[1], Sx = r[2], Sy = r[3], Sxy = r[4], Sxx = r[5];
            float el_err = 0.f, el_valid = 0.f;
            if (cnt >= 2.f) {
                float safe  = fmaxf(cnt, 1.f);
                float eps_m = Sx / safe;
                float sig_m = Sy / safe;
                float cov = Sxy - sig_m * Sx - eps_m * Sy + cnt * eps_m * sig_m;
                float var = Sxx - 2.f * eps_m * Sx + cnt * eps_m * eps_m;
                float et  = E[b] * 1000.f;
                el_err   = fabsf(cov / (var + 1e-8f) - et) / (et + 1e-8f);
                el_valid = 1.f;
            }
            g_samp[0][b] = wmse;
            g_samp[1][b] = el_err;
            g_samp[2][b] = el_valid;
            g_samp[3][b] = r[6];
        }
    } else {
        // ------------- strip of pairs: screen + sparse reduce + accumulate ------
        __shared__ float shp[4][8];
        __shared__ int   s_mat[MAXB];
        __shared__ float s_sr[MAXB];
        __shared__ float s_temp[MAXB];

        const int strip = blockIdx.x - B;
        const int totalPairs = B * B;

        for (int b = tid; b < B; b += 256) {
            s_mat[b]  = mat[b];
            s_sr[b]   = sr[b];
            s_temp[b] = temp[b];
        }
        __syncthreads();

        // each thread screens exactly one pair (fixed map)
        const int idx = strip * STRIP + tid;
        bool t_ij = false, s_ji = false;
        int  myi = 0, myj = 0;
        if (idx < totalPairs) {
            myi = idx / B;
            myj = idx - myi * B;
            bool sd, td;
            pair_masks(s_mat[myi], s_mat[myj], s_sr[myi], s_sr[myj],
                       s_temp[myi], s_temp[myj], t_ij, sd);
            pair_masks(s_mat[myj], s_mat[myi], s_sr[myj], s_sr[myi],
                       s_temp[myj], s_temp[myi], td, s_ji);
        }
        const bool need = t_ij || s_ji;

        // ballot-walk survivors in lane order (deterministic)
        unsigned bal = __ballot_sync(0xFFFFFFFFu, need);
        float tsum = 0.f, tcnt = 0.f, ssum = 0.f, scnt = 0.f;
        const int S4 = S >> 2;
        while (bal) {
            const int src = __ffs(bal) - 1;
            bal &= bal - 1;
            const int i  = __shfl_sync(0xFFFFFFFFu, myi, src);
            const int j  = __shfl_sync(0xFFFFFFFFu, myj, src);
            const int tt = __shfl_sync(0xFFFFFFFFu, (int)t_ij, src);
            const int ss = __shfl_sync(0xFFFFFFFFu, (int)s_ji, src);

            const float4* si = reinterpret_cast<const float4*>(pred + (size_t)i * S);
            const float4* sj = reinterpret_cast<const float4*>(pred + (size_t)j * S);
            float acc = 0.f;
            #pragma unroll 4
            for (int k = lane; k < S4; k += 32) {
                float4 a = si[k], bq = sj[k];
                acc += reluf(a.x - bq.x) + reluf(a.y - bq.y)
                     + reluf(a.z - bq.z) + reluf(a.w - bq.w);
            }
            #pragma unroll
            for (int off = 16; off > 0; off >>= 1)
                acc += __shfl_xor_sync(0xFFFFFFFFu, acc, off);
            const float D = acc / (float)S;          // same on all lanes
            if (tt) { tsum += D; tcnt += 1.f; }
            if (ss) { ssum += D; scnt += 1.f; }
        }

        if (lane == 0) {
            shp[0][wid] = tsum; shp[1][wid] = tcnt;
            shp[2][wid] = ssum; shp[3][wid] = scnt;
        }
        __syncthreads();
        if (tid == 0) {
            float r0 = 0.f, r1 = 0.f, r2 = 0.f, r3 = 0.f;
            #pragma unroll
            for (int q = 0; q < 8; q++) {
                r0 += shp[0][q]; r1 += shp[1][q];
                r2 += shp[2][q]; r3 += shp[3][q];
            }
            g_pairAcc[0][strip] = r0;
            g_pairAcc[1][strip] = r1;
            g_pairAcc[2][strip] = r2;
            g_pairAcc[3][strip] = r3;
        }
    }
}

// ============================ kernel 2: final ================================
__global__ void __launch_bounds__(256)
final_kernel(float* __restrict__ out, int B, int S, int nStrips)
{
    const int tid  = threadIdx.x;
    const int lane = tid & 31;
    const int wid  = tid >> 5;

    __shared__ float sh[8][8];

    float acc8[8];   // 0:mse_p 1:el_sum 2:el_cnt 3:mono_p 4:tsum 5:tcnt 6:ssum 7:scnt
    #pragma unroll
    for (int k = 0; k < 8; k++) acc8[k] = 0.f;

    for (int b = tid; b < B; b += 256) {
        acc8[0] += g_samp[0][b];
        acc8[1] += g_samp[1][b];
        acc8[2] += g_samp[2][b];
        acc8[3] += g_samp[3][b];
    }
    for (int s = tid; s < nStrips; s += 256) {
        acc8[4] += g_pairAcc[0][s];
        acc8[5] += g_pairAcc[1][s];
        acc8[6] += g_pairAcc[2][s];
        acc8[7] += g_pairAcc[3][s];
    }

    #pragma unroll
    for (int k = 0; k < 8; k++) {
        #pragma unroll
        for (int off = 16; off > 0; off >>= 1)
            acc8[k] += __shfl_xor_sync(0xFFFFFFFFu, acc8[k], off);
    }
    if (lane == 0) {
        #pragma unroll
        for (int k = 0; k < 8; k++) sh[k][wid] = acc8[k];
    }
    __syncthreads();
    if (tid == 0) {
        float r[8];
        #pragma unroll
        for (int k = 0; k < 8; k++) {
            r[k] = 0.f;
            #pragma unroll
            for (int q = 0; q < 8; q++) r[k] += sh[k][q];
        }
        float mse_loss  = r[0] / (float)B;
        float elastic   = (r[2] > 0.f) ? r[1] / fmaxf(r[2], 1.f) : 0.f;
        float mono      = r[3] / (float)(B * (S - 1));
        float temp_loss = (r[5] > 0.f) ? r[4] / fmaxf(r[5], 1.f) : 0.f;
        float sr_loss   = (r[7] > 0.f) ? r[6] / fmaxf(r[7], 1.f) : 0.f;
        out[0] = ALPHA * mse_loss + BETA * (elastic + mono + temp_loss + sr_loss);
    }
}

// --------------------------------------------------------------------------
extern "C" void kernel_launch(void* const* d_in, const int* in_sizes, int n_in,
                              void* d_out, int out_size)
{
    const float* pred   = (const float*)d_in[0];
    const float* target = (const float*)d_in[1];
    const int*   matid  = (const int*)  d_in[2];
    const float* strain = (const float*)d_in[3];
    const float* E_GPa  = (const float*)d_in[4];
    const float* temp   = (const float*)d_in[5];
    const float* sr     = (const float*)d_in[6];
    const float* mw     = (const float*)d_in[7];
    float* out = (float*)d_out;

    const int B = in_sizes[2];          // material_ids count
    const int S = in_sizes[0] / B;      // pred = B*S

    const int pairStrips = (B * B + STRIP - 1) / STRIP;   // 64 for B=128
    const int grid       = B + pairStrips;                 // 192 blocks

    work_kernel<<<grid, 256>>>(pred, target, matid, strain, E_GPa, temp, sr, mw,
                               B, S);
    final_kernel<<<1, 256>>>(out, B, S, pairStrips);
}